// round 16
// baseline (speedup 1.0000x reference)
#include <cuda_runtime.h>
#include <cuda_fp16.h>
#include <cstdint>
#include <cstring>

#define N_NODES 50000
#define N_EDGES 600000
#define IN_F    256
#define OUT_F   128

#define SCAN_CHUNK   1024
#define NUM_CHUNKS   ((N_NODES + SCAN_CHUNK - 1) / SCAN_CHUNK)   // 49
#define CSR_BLOCKS   NUM_CHUNKS

// Scratch (alloc-free rule: __device__ globals)
__device__ __half g_support_h[(size_t)N_NODES * OUT_F];   // 12.8 MB fp16
__device__ int   g_counts[N_NODES];
__device__ int   g_offsets[N_NODES + 1];
__device__ int   g_cursor[N_NODES];
__device__ int   g_scan_partial[NUM_CHUNKS];
__device__ int   g_bar[4];                              // grid barriers (reset by aggregate)
__device__ int2  g_sorted[N_EDGES];                    // {col, val_bits}

#if defined(__CUDA_ARCH__) && (__CUDA_ARCH__ == 1030) && \
    (defined(__CUDA_ARCH_FEAT_SM103_ALL) || defined(__CUDA_ARCH_SPECIFIC__))
#define GCN_HAS_TCGEN05 1
#else
#define GCN_HAS_TCGEN05 0
#endif

// ===========================================================================
// GEMM: support = x @ W, tcgen05 kind::f16 (fp16 in, fp32 acc). (R15 proven.)
// ===========================================================================

#define K_CHUNK     64
#define NUM_KCHUNK  (IN_F / K_CHUNK)       // 4
#define TILE_BYTES  (128 * K_CHUNK * 2)    // 16384 (fp16 tile)

#define SM_TMEM_PTR 0
#define SM_MBAR     8
#define SM_A        1024
#define SM_B        (SM_A + TILE_BYTES)
#define SM_TOTAL    (SM_B + TILE_BYTES)    // 33792 (~33 KB)

#define F16_IDESC   0x8200010u

#define DESC_BASE   0x4000404000010000ull
#define MAKE_DESC(a) (DESC_BASE | (uint64_t)(((a) >> 4) & 0x3FFF))

__device__ __forceinline__ uint32_t smem_u32(const void* p) {
    uint32_t a;
    asm("{ .reg .u64 t; cvta.to.shared.u64 t, %1; cvt.u32.u64 %0, t; }"
        : "=r"(a) : "l"(p));
    return a;
}

__device__ __forceinline__ uint32_t h2_bits(__half2 h) {
    uint32_t u;
    memcpy(&u, &h, 4);
    return u;
}

#if GCN_HAS_TCGEN05
__device__ __forceinline__ uint32_t elect_one() {
    uint32_t p;
    asm volatile("{ .reg .pred p; elect.sync _|p, 0xFFFFFFFF; selp.b32 %0,1,0,p; }"
                 : "=r"(p));
    return p;
}

__device__ __forceinline__ void mma_f16_ss(uint32_t d_tmem, uint64_t a_desc,
                                           uint64_t b_desc, uint32_t idesc,
                                           uint32_t enable_d) {
    asm volatile(
        "{\n\t.reg .pred p;\n\tsetp.ne.u32 p, %4, 0;\n\t"
        "tcgen05.mma.cta_group::1.kind::f16 [%0], %1, %2, %3, {%5,%5,%5,%5}, p;\n\t}"
        :: "r"(d_tmem), "l"(a_desc), "l"(b_desc), "r"(idesc),
           "r"(enable_d), "r"(0u)
        : "memory");
}

__device__ __forceinline__ void mbar_wait(uint32_t addr, uint32_t parity) {
    uint32_t done;
    asm volatile(
        "{\n\t.reg .pred p;\n\t"
        "mbarrier.try_wait.parity.acquire.cta.shared::cta.b64 p, [%1], %2;\n\t"
        "selp.b32 %0, 1, 0, p;\n\t}"
        : "=r"(done) : "r"(addr), "r"(parity) : "memory");
    while (!done) {
        asm volatile(
            "{\n\t.reg .pred p;\n\t"
            "mbarrier.try_wait.parity.acquire.cta.shared::cta.b64 p, [%1], %2, 0x989680;\n\t"
            "selp.b32 %0, 1, 0, p;\n\t}"
            : "=r"(done) : "r"(addr), "r"(parity) : "memory");
    }
}

__device__ __forceinline__ uint32_t swz(uint32_t b) {
    return b ^ ((b >> 3) & 0x70);
}

// SW128 atom byte offset for fp16 element (row, col) in a 128 x 64 fp16 tile
__device__ __forceinline__ uint32_t tile_off_h(int row, int col) {
    uint32_t byte = (uint32_t)((row >> 3) * 1024 + (row & 7) * 128 + col * 2);
    return swz(byte);
}
#endif  // GCN_HAS_TCGEN05

__global__ __launch_bounds__(256) void gcn_gemm_tc_kernel(
    const float* __restrict__ x,
    const float* __restrict__ w)
{
    extern __shared__ char smem[];
    const int tid  = threadIdx.x;
    const int block_row = blockIdx.x * 128;

#if GCN_HAS_TCGEN05
    const uint32_t sbase = smem_u32(smem);
    const int wid  = tid >> 5;
    const int lane = tid & 31;

    if (wid == 0) {
        asm volatile("tcgen05.alloc.cta_group::1.sync.aligned.shared::cta.b32 [%0], %1;"
                     :: "r"(sbase + SM_TMEM_PTR), "r"(128u) : "memory");
        asm volatile("tcgen05.relinquish_alloc_permit.cta_group::1.sync.aligned;");
    }
    if (tid == 0) {
        asm volatile("mbarrier.init.shared.b64 [%0], %1;"
                     :: "r"(sbase + SM_MBAR), "r"(1u) : "memory");
    }
    __syncthreads();

    uint32_t tmem;
    asm volatile("ld.shared.b32 %0, [%1];" : "=r"(tmem) : "r"(sbase + SM_TMEM_PTR));

    const int a_row = tid >> 4;          // 0..15
    const int a_c4  = (tid & 15) * 4;    // 0..60
    const int b_n   = tid & 127;
    const int b_kg0 = tid >> 7;          // 0 or 1

    for (int kc = 0; kc < NUM_KCHUNK; kc++) {
        const int kb = kc * K_CHUNK;

        float4 a_pre[8];
        float4 b_pre[8];
        #pragma unroll
        for (int p = 0; p < 8; p++) {
            const int row = a_row + p * 16;
            const int gr  = block_row + row;
            a_pre[p] = make_float4(0.f, 0.f, 0.f, 0.f);
            if (gr < N_NODES)
                a_pre[p] = *(const float4*)(x + (size_t)gr * IN_F + kb + a_c4);
        }
        #pragma unroll
        for (int p = 0; p < 8; p++) {
            const int kg = b_kg0 + p * 2;            // 0..15
            const float* wp = w + (size_t)(kb + kg * 4) * OUT_F + b_n;
            b_pre[p].x = __ldg(wp);
            b_pre[p].y = __ldg(wp + OUT_F);
            b_pre[p].z = __ldg(wp + 2 * OUT_F);
            b_pre[p].w = __ldg(wp + 3 * OUT_F);
        }

        if (kc >= 1)
            mbar_wait(sbase + SM_MBAR, (uint32_t)((kc - 1) & 1));

        #pragma unroll
        for (int p = 0; p < 8; p++) {
            const int row = a_row + p * 16;
            const float4 v = a_pre[p];
            const uint32_t o = tile_off_h(row, a_c4);
            *(uint2*)(smem + SM_A + o) = make_uint2(
                h2_bits(__floats2half2_rn(v.x, v.y)),
                h2_bits(__floats2half2_rn(v.z, v.w)));
        }
        #pragma unroll
        for (int p = 0; p < 8; p++) {
            const int kg = b_kg0 + p * 2;
            const float4 v = b_pre[p];
            const uint32_t o = tile_off_h(b_n, kg * 4);
            *(uint2*)(smem + SM_B + o) = make_uint2(
                h2_bits(__floats2half2_rn(v.x, v.y)),
                h2_bits(__floats2half2_rn(v.z, v.w)));
        }
        asm volatile("fence.proxy.async.shared::cta;" ::: "memory");
        __syncthreads();

        if (wid == 0 && elect_one()) {
            const uint64_t ad = MAKE_DESC(sbase + SM_A);
            const uint64_t bd = MAKE_DESC(sbase + SM_B);
            #pragma unroll
            for (int s = 0; s < K_CHUNK / 16; s++) {
                const uint64_t off = (uint64_t)(s * 2);   // 32B per step
                const uint32_t first = (kc == 0 && s == 0) ? 0u : 1u;
                mma_f16_ss(tmem, ad + off, bd + off, F16_IDESC, first);
            }
            asm volatile(
                "tcgen05.commit.cta_group::1.mbarrier::arrive::one.shared::cluster.b64 [%0];"
                :: "r"(sbase + SM_MBAR) : "memory");
        }
    }

    mbar_wait(sbase + SM_MBAR, 1u);
    asm volatile("tcgen05.fence::after_thread_sync;" ::: "memory");

    {
        const int sub  = wid & 3;
        const int half = wid >> 2;
        uint32_t d[64];
        const uint32_t taddr = tmem + half * 64;
        asm volatile(
            "tcgen05.ld.sync.aligned.32x32b.x32.b32 "
            "{%0,%1,%2,%3,%4,%5,%6,%7,%8,%9,%10,%11,%12,%13,%14,%15,"
            "%16,%17,%18,%19,%20,%21,%22,%23,%24,%25,%26,%27,%28,%29,%30,%31}, [%32];"
            : "=r"(d[0]),"=r"(d[1]),"=r"(d[2]),"=r"(d[3]),"=r"(d[4]),"=r"(d[5]),"=r"(d[6]),"=r"(d[7]),
              "=r"(d[8]),"=r"(d[9]),"=r"(d[10]),"=r"(d[11]),"=r"(d[12]),"=r"(d[13]),"=r"(d[14]),"=r"(d[15]),
              "=r"(d[16]),"=r"(d[17]),"=r"(d[18]),"=r"(d[19]),"=r"(d[20]),"=r"(d[21]),"=r"(d[22]),"=r"(d[23]),
              "=r"(d[24]),"=r"(d[25]),"=r"(d[26]),"=r"(d[27]),"=r"(d[28]),"=r"(d[29]),"=r"(d[30]),"=r"(d[31])
            : "r"(taddr));
        asm volatile(
            "tcgen05.ld.sync.aligned.32x32b.x32.b32 "
            "{%0,%1,%2,%3,%4,%5,%6,%7,%8,%9,%10,%11,%12,%13,%14,%15,"
            "%16,%17,%18,%19,%20,%21,%22,%23,%24,%25,%26,%27,%28,%29,%30,%31}, [%32];"
            : "=r"(d[32]),"=r"(d[33]),"=r"(d[34]),"=r"(d[35]),"=r"(d[36]),"=r"(d[37]),"=r"(d[38]),"=r"(d[39]),
              "=r"(d[40]),"=r"(d[41]),"=r"(d[42]),"=r"(d[43]),"=r"(d[44]),"=r"(d[45]),"=r"(d[46]),"=r"(d[47]),
              "=r"(d[48]),"=r"(d[49]),"=r"(d[50]),"=r"(d[51]),"=r"(d[52]),"=r"(d[53]),"=r"(d[54]),"=r"(d[55]),
              "=r"(d[56]),"=r"(d[57]),"=r"(d[58]),"=r"(d[59]),"=r"(d[60]),"=r"(d[61]),"=r"(d[62]),"=r"(d[63])
            : "r"(taddr + 32));
        asm volatile("tcgen05.wait::ld.sync.aligned;" ::: "memory");

        const int gr = block_row + sub * 32 + lane;
        if (gr < N_NODES) {
            uint2* sp = (uint2*)(g_support_h + (size_t)gr * OUT_F + half * 64);
            #pragma unroll
            for (int q = 0; q < 16; q++) {
                __half2 h0 = __floats2half2_rn(__uint_as_float(d[q * 4 + 0]),
                                               __uint_as_float(d[q * 4 + 1]));
                __half2 h1 = __floats2half2_rn(__uint_as_float(d[q * 4 + 2]),
                                               __uint_as_float(d[q * 4 + 3]));
                sp[q] = make_uint2(h2_bits(h0), h2_bits(h1));
            }
        }
    }

    __syncthreads();
    if (tid == 0) {
        asm volatile("mbarrier.inval.shared.b64 [%0];" :: "r"(sbase + SM_MBAR) : "memory");
    }
    if (wid == 0) {
        asm volatile("tcgen05.dealloc.cta_group::1.sync.aligned.b32 %0, %1;"
                     :: "r"(tmem), "r"(128u));
    }

#else
    // ---------------- FFMA fallback (family compute_103 pass) ----------------
    const int BK = 16;
    float* As = (float*)smem;
    float* Bs = As + BK * 128;

    const int tx = tid & 15;
    const int ty = tid >> 4;
    const int a_row = tid >> 1;
    const int a_col = (tid & 1) * 8;
    const int b_row = tid >> 4;
    const int b_col = (tid & 15) * 8;

    float acc[8][8];
    #pragma unroll
    for (int i = 0; i < 8; i++)
        #pragma unroll
        for (int j = 0; j < 8; j++)
            acc[i][j] = 0.0f;

    const int g_arow = block_row + a_row;
    const bool a_valid = (g_arow < N_NODES);

    for (int kt = 0; kt < IN_F; kt += BK) {
        {
            float4 v0, v1;
            if (a_valid) {
                const float* xp = x + (size_t)g_arow * IN_F + kt + a_col;
                v0 = *(const float4*)(xp);
                v1 = *(const float4*)(xp + 4);
            } else {
                v0 = make_float4(0.f, 0.f, 0.f, 0.f);
                v1 = v0;
            }
            As[(a_col + 0) * 128 + a_row] = v0.x;
            As[(a_col + 1) * 128 + a_row] = v0.y;
            As[(a_col + 2) * 128 + a_row] = v0.z;
            As[(a_col + 3) * 128 + a_row] = v0.w;
            As[(a_col + 4) * 128 + a_row] = v1.x;
            As[(a_col + 5) * 128 + a_row] = v1.y;
            As[(a_col + 6) * 128 + a_row] = v1.z;
            As[(a_col + 7) * 128 + a_row] = v1.w;
        }
        {
            const float* wp = w + (size_t)(kt + b_row) * OUT_F + b_col;
            float4 v0 = *(const float4*)(wp);
            float4 v1 = *(const float4*)(wp + 4);
            *(float4*)(&Bs[b_row * 128 + b_col])     = v0;
            *(float4*)(&Bs[b_row * 128 + b_col + 4]) = v1;
        }
        __syncthreads();

        #pragma unroll
        for (int k = 0; k < BK; k++) {
            float a[8], b[8];
            float4 av0 = *(const float4*)(&As[k * 128 + ty * 8]);
            float4 av1 = *(const float4*)(&As[k * 128 + ty * 8 + 4]);
            float4 bv0 = *(const float4*)(&Bs[k * 128 + tx * 8]);
            float4 bv1 = *(const float4*)(&Bs[k * 128 + tx * 8 + 4]);
            a[0]=av0.x; a[1]=av0.y; a[2]=av0.z; a[3]=av0.w;
            a[4]=av1.x; a[5]=av1.y; a[6]=av1.z; a[7]=av1.w;
            b[0]=bv0.x; b[1]=bv0.y; b[2]=bv0.z; b[3]=bv0.w;
            b[4]=bv1.x; b[5]=bv1.y; b[6]=bv1.z; b[7]=bv1.w;
            #pragma unroll
            for (int i = 0; i < 8; i++)
                #pragma unroll
                for (int j = 0; j < 8; j++)
                    acc[i][j] = fmaf(a[i], b[j], acc[i][j]);
        }
        __syncthreads();
    }

    #pragma unroll
    for (int i = 0; i < 8; i++) {
        const int gr = block_row + ty * 8 + i;
        if (gr < N_NODES) {
            uint2* sp = (uint2*)(g_support_h + (size_t)gr * OUT_F + tx * 8);
            __half2 h0 = __floats2half2_rn(acc[i][0], acc[i][1]);
            __half2 h1 = __floats2half2_rn(acc[i][2], acc[i][3]);
            __half2 h2 = __floats2half2_rn(acc[i][4], acc[i][5]);
            __half2 h3 = __floats2half2_rn(acc[i][6], acc[i][7]);
            sp[0] = make_uint2(h2_bits(h0), h2_bits(h1));
            sp[1] = make_uint2(h2_bits(h2), h2_bits(h3));
        }
    }
#endif
}

// ---------------------------------------------------------------------------
// Fused CSR build: zero + histogram + scan + permute in ONE kernel.
// grid = 49 blocks x 1024 (all co-resident on 148 SMs -> spin-safe).
// Grid barriers: monotonic counters within a launch; RESET BY AGGREGATE
// (strictly-after kernel) so each replay starts from zero without a
// reset-while-spinning hazard.
// ---------------------------------------------------------------------------
__device__ __forceinline__ void grid_bar(int idx)
{
    __threadfence();
    __syncthreads();
    if (threadIdx.x == 0) {
        atomicAdd(&g_bar[idx], 1);
        while (atomicAdd(&g_bar[idx], 0) < CSR_BLOCKS) {}
    }
    __syncthreads();
}

__global__ __launch_bounds__(1024) void gcn_csr_build_kernel(
    const int*   __restrict__ edge_rows,
    const int*   __restrict__ edge_cols,
    const float* __restrict__ edge_vals)
{
    __shared__ int warp_sums[32];
    __shared__ int s_total;
    __shared__ int s_base;

    const int bid  = blockIdx.x;
    const int tid  = threadIdx.x;
    const int lane = tid & 31;
    const int warp = tid >> 5;
    const int gt   = bid * SCAN_CHUNK + tid;
    const int gsz  = CSR_BLOCKS * SCAN_CHUNK;

    // phase 0: zero counts (own chunk)
    if (gt < N_NODES) g_counts[gt] = 0;
    grid_bar(0);

    // phase 1: histogram (edges strided across grid)
    for (int e = gt; e < N_EDGES; e += gsz)
        atomicAdd(&g_counts[edge_rows[e]], 1);
    grid_bar(1);

    // phase 2a: block-local scan of own chunk; publish block total
    int v = (gt < N_NODES) ? __ldcg(&g_counts[gt]) : 0;
    int incl = v;
    #pragma unroll
    for (int off = 1; off < 32; off <<= 1) {
        int t = __shfl_up_sync(0xffffffffu, incl, off);
        if (lane >= off) incl += t;
    }
    if (lane == 31) warp_sums[warp] = incl;
    __syncthreads();
    if (warp == 0) {
        int w = warp_sums[lane];
        int wi = w;
        #pragma unroll
        for (int off = 1; off < 32; off <<= 1) {
            int t = __shfl_up_sync(0xffffffffu, wi, off);
            if (lane >= off) wi += t;
        }
        if (lane == 31) s_total = wi;
        warp_sums[lane] = wi - w;          // exclusive warp bases
    }
    __syncthreads();
    if (tid == 0) g_scan_partial[bid] = s_total;
    grid_bar(2);

    // phase 2b: base = sum of predecessors' totals; write offsets + cursor
    if (warp == 0) {
        int base = 0;
        for (int b = lane; b < bid; b += 32)
            base += __ldcg(&g_scan_partial[b]);
        #pragma unroll
        for (int off = 16; off > 0; off >>= 1)
            base += __shfl_down_sync(0xffffffffu, base, off);
        if (lane == 0) s_base = base;
    }
    __syncthreads();
    if (gt < N_NODES) {
        int o = s_base + warp_sums[warp] + (incl - v);
        g_offsets[gt] = o;
        g_cursor[gt]  = o;
    }
    if (bid == CSR_BLOCKS - 1 && tid == 0)
        g_offsets[N_NODES] = s_base + s_total;
    grid_bar(3);

    // phase 3: permute (edges strided across grid)
    for (int e = gt; e < N_EDGES; e += gsz) {
        int r = edge_rows[e];
        int pos = atomicAdd(&g_cursor[r], 1);
        g_sorted[pos] = make_int2(edge_cols[e], __float_as_int(edge_vals[e]));
    }
}

// ---------------------------------------------------------------------------
// Aggregate: one warp per node; fp16 gathers, fp32 accumulation.
// Also resets the CSR grid-barrier counters for the next replay.
// ---------------------------------------------------------------------------
__device__ __forceinline__ void agg_fma(float4& acc, float v, uint2 m)
{
    __half2 ha, hb;
    memcpy(&ha, &m.x, 4);
    memcpy(&hb, &m.y, 4);
    const float2 fa = __half22float2(ha);
    const float2 fb = __half22float2(hb);
    acc.x = fmaf(v, fa.x, acc.x);
    acc.y = fmaf(v, fa.y, acc.y);
    acc.z = fmaf(v, fb.x, acc.z);
    acc.w = fmaf(v, fb.y, acc.w);
}

__global__ __launch_bounds__(256) void gcn_aggregate_kernel(
    float* __restrict__ out,
    const float* __restrict__ bias)
{
    // Reset CSR grid barriers (CSR kernel has fully completed before this
    // kernel starts; next replay needs zeros).
    if (blockIdx.x == 0 && threadIdx.x < 4)
        g_bar[threadIdx.x] = 0;

    const int warp_id = (blockIdx.x * blockDim.x + threadIdx.x) >> 5;
    const int lane    = threadIdx.x & 31;
    if (warp_id >= N_NODES) return;

    const int start = g_offsets[warp_id];
    const int end   = g_offsets[warp_id + 1];

    float4 acc = make_float4(0.f, 0.f, 0.f, 0.f);
    const uint2* sup = (const uint2*)g_support_h;   // 32 uint2 per node row

    for (int base = start; base < end; base += 32) {
        const int n = min(32, end - base);
        int2 ev = make_int2(0, 0);
        if (lane < n)
            ev = __ldg(&g_sorted[base + lane]);
        const int   c = ev.x;
        const float v = __int_as_float(ev.y);

        int j = 0;
        for (; j + 4 <= n; j += 4) {
            const int   c0 = __shfl_sync(0xffffffffu, c, j + 0);
            const int   c1 = __shfl_sync(0xffffffffu, c, j + 1);
            const int   c2 = __shfl_sync(0xffffffffu, c, j + 2);
            const int   c3 = __shfl_sync(0xffffffffu, c, j + 3);
            const float v0 = __shfl_sync(0xffffffffu, v, j + 0);
            const float v1 = __shfl_sync(0xffffffffu, v, j + 1);
            const float v2 = __shfl_sync(0xffffffffu, v, j + 2);
            const float v3 = __shfl_sync(0xffffffffu, v, j + 3);
            const uint2 m0 = __ldg(sup + (size_t)c0 * 32 + lane);
            const uint2 m1 = __ldg(sup + (size_t)c1 * 32 + lane);
            const uint2 m2 = __ldg(sup + (size_t)c2 * 32 + lane);
            const uint2 m3 = __ldg(sup + (size_t)c3 * 32 + lane);
            agg_fma(acc, v0, m0);
            agg_fma(acc, v1, m1);
            agg_fma(acc, v2, m2);
            agg_fma(acc, v3, m3);
        }
        for (; j < n; j++) {
            const int   cj = __shfl_sync(0xffffffffu, c, j);
            const float vj = __shfl_sync(0xffffffffu, v, j);
            const uint2 m = __ldg(sup + (size_t)cj * 32 + lane);
            agg_fma(acc, vj, m);
        }
    }

    const float4 b = __ldg(((const float4*)bias) + lane);
    acc.x += b.x; acc.y += b.y; acc.z += b.z; acc.w += b.w;
    ((float4*)out)[(size_t)warp_id * 32 + lane] = acc;
}

// ---------------------------------------------------------------------------
// kernel_launch: GEMM on main stream; fused CSR build on side stream;
// join before aggregate. 3 kernels total.
// Inputs (metadata order): x, edge_rows, edge_cols, edge_vals, weight, bias
// ---------------------------------------------------------------------------
extern "C" void kernel_launch(void* const* d_in, const int* in_sizes, int n_in,
                              void* d_out, int out_size)
{
    const float* x         = (const float*)d_in[0];
    const int*   edge_rows = (const int*)  d_in[1];
    const int*   edge_cols = (const int*)  d_in[2];
    const float* edge_vals = (const float*)d_in[3];
    const float* weight    = (const float*)d_in[4];
    const float* bias      = (const float*)d_in[5];
    float*       out       = (float*)d_out;

    static cudaStream_t s_side = nullptr;
    static cudaEvent_t  ev_fork = nullptr;
    static cudaEvent_t  ev_join = nullptr;
    if (s_side == nullptr) {
        cudaStreamCreateWithFlags(&s_side, cudaStreamNonBlocking);
        cudaEventCreateWithFlags(&ev_fork, cudaEventDisableTiming);
        cudaEventCreateWithFlags(&ev_join, cudaEventDisableTiming);
        cudaFuncSetAttribute(gcn_gemm_tc_kernel,
                             cudaFuncAttributeMaxDynamicSharedMemorySize, SM_TOTAL);
    }

    // Fork
    cudaEventRecord(ev_fork, 0);
    cudaStreamWaitEvent(s_side, ev_fork, 0);

    // Branch A (main): GEMM
    gcn_gemm_tc_kernel<<<(N_NODES + 127) / 128, 256, SM_TOTAL>>>(x, weight);

    // Branch B (side): fused CSR build (single launch)
    gcn_csr_build_kernel<<<CSR_BLOCKS, 1024, 0, s_side>>>(
        edge_rows, edge_cols, edge_vals);
    cudaEventRecord(ev_join, s_side);

    // Join + aggregate
    cudaStreamWaitEvent(0, ev_join, 0);
    {
        const int warps_per_block = 256 / 32;
        const int blocks = (N_NODES + warps_per_block - 1) / warps_per_block;
        gcn_aggregate_kernel<<<blocks, 256>>>(out, bias);
    }
}

// round 17
// speedup vs baseline: 1.1159x; 1.1159x over previous
#include <cuda_runtime.h>
#include <cuda_fp16.h>
#include <cstdint>
#include <cstring>

#define N_NODES 50000
#define N_EDGES 600000
#define IN_F    256
#define OUT_F   128

#define SCAN_CHUNK   1024
#define NUM_CHUNKS   ((N_NODES + SCAN_CHUNK - 1) / SCAN_CHUNK)   // 49

// Scratch (alloc-free rule: __device__ globals; zero-initialized at load)
__device__ __half g_support_h[(size_t)N_NODES * OUT_F];   // 12.8 MB fp16
__device__ int   g_counts[N_NODES];      // zeroed by scan for next replay
__device__ int   g_offsets[N_NODES + 1];
__device__ int   g_cursor[N_NODES];
__device__ volatile int g_scan_partial[NUM_CHUNKS];
__device__ int   g_scan_flag[NUM_CHUNKS]; // reset by aggregate for next replay
__device__ int2  g_sorted[N_EDGES];      // {col, val_bits}

#if defined(__CUDA_ARCH__) && (__CUDA_ARCH__ == 1030) && \
    (defined(__CUDA_ARCH_FEAT_SM103_ALL) || defined(__CUDA_ARCH_SPECIFIC__))
#define GCN_HAS_TCGEN05 1
#else
#define GCN_HAS_TCGEN05 0
#endif

// ===========================================================================
// GEMM: support = x @ W, tcgen05 kind::f16 (fp16 in, fp32 acc). (R15 proven.)
// K_CHUNK=64 (4 chunks), fp16 tiles -> 33 KB SMEM, 3 CTAs/SM single wave.
// ===========================================================================

#define K_CHUNK     64
#define NUM_KCHUNK  (IN_F / K_CHUNK)       // 4
#define TILE_BYTES  (128 * K_CHUNK * 2)    // 16384 (fp16 tile)

#define SM_TMEM_PTR 0
#define SM_MBAR     8
#define SM_A        1024
#define SM_B        (SM_A + TILE_BYTES)
#define SM_TOTAL    (SM_B + TILE_BYTES)    // 33792 (~33 KB)

#define F16_IDESC   0x8200010u

#define DESC_BASE   0x4000404000010000ull
#define MAKE_DESC(a) (DESC_BASE | (uint64_t)(((a) >> 4) & 0x3FFF))

__device__ __forceinline__ uint32_t smem_u32(const void* p) {
    uint32_t a;
    asm("{ .reg .u64 t; cvta.to.shared.u64 t, %1; cvt.u32.u64 %0, t; }"
        : "=r"(a) : "l"(p));
    return a;
}

__device__ __forceinline__ uint32_t h2_bits(__half2 h) {
    uint32_t u;
    memcpy(&u, &h, 4);
    return u;
}

#if GCN_HAS_TCGEN05
__device__ __forceinline__ uint32_t elect_one() {
    uint32_t p;
    asm volatile("{ .reg .pred p; elect.sync _|p, 0xFFFFFFFF; selp.b32 %0,1,0,p; }"
                 : "=r"(p));
    return p;
}

__device__ __forceinline__ void mma_f16_ss(uint32_t d_tmem, uint64_t a_desc,
                                           uint64_t b_desc, uint32_t idesc,
                                           uint32_t enable_d) {
    asm volatile(
        "{\n\t.reg .pred p;\n\tsetp.ne.u32 p, %4, 0;\n\t"
        "tcgen05.mma.cta_group::1.kind::f16 [%0], %1, %2, %3, {%5,%5,%5,%5}, p;\n\t}"
        :: "r"(d_tmem), "l"(a_desc), "l"(b_desc), "r"(idesc),
           "r"(enable_d), "r"(0u)
        : "memory");
}

__device__ __forceinline__ void mbar_wait(uint32_t addr, uint32_t parity) {
    uint32_t done;
    asm volatile(
        "{\n\t.reg .pred p;\n\t"
        "mbarrier.try_wait.parity.acquire.cta.shared::cta.b64 p, [%1], %2;\n\t"
        "selp.b32 %0, 1, 0, p;\n\t}"
        : "=r"(done) : "r"(addr), "r"(parity) : "memory");
    while (!done) {
        asm volatile(
            "{\n\t.reg .pred p;\n\t"
            "mbarrier.try_wait.parity.acquire.cta.shared::cta.b64 p, [%1], %2, 0x989680;\n\t"
            "selp.b32 %0, 1, 0, p;\n\t}"
            : "=r"(done) : "r"(addr), "r"(parity) : "memory");
    }
}

__device__ __forceinline__ uint32_t swz(uint32_t b) {
    return b ^ ((b >> 3) & 0x70);
}

// SW128 atom byte offset for fp16 element (row, col) in a 128 x 64 fp16 tile
__device__ __forceinline__ uint32_t tile_off_h(int row, int col) {
    uint32_t byte = (uint32_t)((row >> 3) * 1024 + (row & 7) * 128 + col * 2);
    return swz(byte);
}
#endif  // GCN_HAS_TCGEN05

__global__ __launch_bounds__(256) void gcn_gemm_tc_kernel(
    const float* __restrict__ x,
    const float* __restrict__ w)
{
    extern __shared__ char smem[];
    const int tid  = threadIdx.x;
    const int block_row = blockIdx.x * 128;

#if GCN_HAS_TCGEN05
    const uint32_t sbase = smem_u32(smem);
    const int wid  = tid >> 5;
    const int lane = tid & 31;

    if (wid == 0) {
        asm volatile("tcgen05.alloc.cta_group::1.sync.aligned.shared::cta.b32 [%0], %1;"
                     :: "r"(sbase + SM_TMEM_PTR), "r"(128u) : "memory");
        asm volatile("tcgen05.relinquish_alloc_permit.cta_group::1.sync.aligned;");
    }
    if (tid == 0) {
        asm volatile("mbarrier.init.shared.b64 [%0], %1;"
                     :: "r"(sbase + SM_MBAR), "r"(1u) : "memory");
    }
    __syncthreads();

    uint32_t tmem;
    asm volatile("ld.shared.b32 %0, [%1];" : "=r"(tmem) : "r"(sbase + SM_TMEM_PTR));

    const int a_row = tid >> 4;          // 0..15
    const int a_c4  = (tid & 15) * 4;    // 0..60
    const int b_n   = tid & 127;
    const int b_kg0 = tid >> 7;          // 0 or 1

    for (int kc = 0; kc < NUM_KCHUNK; kc++) {
        const int kb = kc * K_CHUNK;

        float4 a_pre[8];
        float4 b_pre[8];
        #pragma unroll
        for (int p = 0; p < 8; p++) {
            const int row = a_row + p * 16;
            const int gr  = block_row + row;
            a_pre[p] = make_float4(0.f, 0.f, 0.f, 0.f);
            if (gr < N_NODES)
                a_pre[p] = *(const float4*)(x + (size_t)gr * IN_F + kb + a_c4);
        }
        #pragma unroll
        for (int p = 0; p < 8; p++) {
            const int kg = b_kg0 + p * 2;            // 0..15
            const float* wp = w + (size_t)(kb + kg * 4) * OUT_F + b_n;
            b_pre[p].x = __ldg(wp);
            b_pre[p].y = __ldg(wp + OUT_F);
            b_pre[p].z = __ldg(wp + 2 * OUT_F);
            b_pre[p].w = __ldg(wp + 3 * OUT_F);
        }

        if (kc >= 1)
            mbar_wait(sbase + SM_MBAR, (uint32_t)((kc - 1) & 1));

        #pragma unroll
        for (int p = 0; p < 8; p++) {
            const int row = a_row + p * 16;
            const float4 v = a_pre[p];
            const uint32_t o = tile_off_h(row, a_c4);
            *(uint2*)(smem + SM_A + o) = make_uint2(
                h2_bits(__floats2half2_rn(v.x, v.y)),
                h2_bits(__floats2half2_rn(v.z, v.w)));
        }
        #pragma unroll
        for (int p = 0; p < 8; p++) {
            const int kg = b_kg0 + p * 2;
            const float4 v = b_pre[p];
            const uint32_t o = tile_off_h(b_n, kg * 4);
            *(uint2*)(smem + SM_B + o) = make_uint2(
                h2_bits(__floats2half2_rn(v.x, v.y)),
                h2_bits(__floats2half2_rn(v.z, v.w)));
        }
        asm volatile("fence.proxy.async.shared::cta;" ::: "memory");
        __syncthreads();

        if (wid == 0 && elect_one()) {
            const uint64_t ad = MAKE_DESC(sbase + SM_A);
            const uint64_t bd = MAKE_DESC(sbase + SM_B);
            #pragma unroll
            for (int s = 0; s < K_CHUNK / 16; s++) {
                const uint64_t off = (uint64_t)(s * 2);   // 32B per step
                const uint32_t first = (kc == 0 && s == 0) ? 0u : 1u;
                mma_f16_ss(tmem, ad + off, bd + off, F16_IDESC, first);
            }
            asm volatile(
                "tcgen05.commit.cta_group::1.mbarrier::arrive::one.shared::cluster.b64 [%0];"
                :: "r"(sbase + SM_MBAR) : "memory");
        }
    }

    mbar_wait(sbase + SM_MBAR, 1u);
    asm volatile("tcgen05.fence::after_thread_sync;" ::: "memory");

    {
        const int sub  = wid & 3;
        const int half = wid >> 2;
        uint32_t d[64];
        const uint32_t taddr = tmem + half * 64;
        asm volatile(
            "tcgen05.ld.sync.aligned.32x32b.x32.b32 "
            "{%0,%1,%2,%3,%4,%5,%6,%7,%8,%9,%10,%11,%12,%13,%14,%15,"
            "%16,%17,%18,%19,%20,%21,%22,%23,%24,%25,%26,%27,%28,%29,%30,%31}, [%32];"
            : "=r"(d[0]),"=r"(d[1]),"=r"(d[2]),"=r"(d[3]),"=r"(d[4]),"=r"(d[5]),"=r"(d[6]),"=r"(d[7]),
              "=r"(d[8]),"=r"(d[9]),"=r"(d[10]),"=r"(d[11]),"=r"(d[12]),"=r"(d[13]),"=r"(d[14]),"=r"(d[15]),
              "=r"(d[16]),"=r"(d[17]),"=r"(d[18]),"=r"(d[19]),"=r"(d[20]),"=r"(d[21]),"=r"(d[22]),"=r"(d[23]),
              "=r"(d[24]),"=r"(d[25]),"=r"(d[26]),"=r"(d[27]),"=r"(d[28]),"=r"(d[29]),"=r"(d[30]),"=r"(d[31])
            : "r"(taddr));
        asm volatile(
            "tcgen05.ld.sync.aligned.32x32b.x32.b32 "
            "{%0,%1,%2,%3,%4,%5,%6,%7,%8,%9,%10,%11,%12,%13,%14,%15,"
            "%16,%17,%18,%19,%20,%21,%22,%23,%24,%25,%26,%27,%28,%29,%30,%31}, [%32];"
            : "=r"(d[32]),"=r"(d[33]),"=r"(d[34]),"=r"(d[35]),"=r"(d[36]),"=r"(d[37]),"=r"(d[38]),"=r"(d[39]),
              "=r"(d[40]),"=r"(d[41]),"=r"(d[42]),"=r"(d[43]),"=r"(d[44]),"=r"(d[45]),"=r"(d[46]),"=r"(d[47]),
              "=r"(d[48]),"=r"(d[49]),"=r"(d[50]),"=r"(d[51]),"=r"(d[52]),"=r"(d[53]),"=r"(d[54]),"=r"(d[55]),
              "=r"(d[56]),"=r"(d[57]),"=r"(d[58]),"=r"(d[59]),"=r"(d[60]),"=r"(d[61]),"=r"(d[62]),"=r"(d[63])
            : "r"(taddr + 32));
        asm volatile("tcgen05.wait::ld.sync.aligned;" ::: "memory");

        const int gr = block_row + sub * 32 + lane;
        if (gr < N_NODES) {
            uint2* sp = (uint2*)(g_support_h + (size_t)gr * OUT_F + half * 64);
            #pragma unroll
            for (int q = 0; q < 16; q++) {
                __half2 h0 = __floats2half2_rn(__uint_as_float(d[q * 4 + 0]),
                                               __uint_as_float(d[q * 4 + 1]));
                __half2 h1 = __floats2half2_rn(__uint_as_float(d[q * 4 + 2]),
                                               __uint_as_float(d[q * 4 + 3]));
                sp[q] = make_uint2(h2_bits(h0), h2_bits(h1));
            }
        }
    }

    __syncthreads();
    if (tid == 0) {
        asm volatile("mbarrier.inval.shared.b64 [%0];" :: "r"(sbase + SM_MBAR) : "memory");
    }
    if (wid == 0) {
        asm volatile("tcgen05.dealloc.cta_group::1.sync.aligned.b32 %0, %1;"
                     :: "r"(tmem), "r"(128u));
    }

#else
    // ---------------- FFMA fallback (family compute_103 pass) ----------------
    const int BK = 16;
    float* As = (float*)smem;
    float* Bs = As + BK * 128;

    const int tx = tid & 15;
    const int ty = tid >> 4;
    const int a_row = tid >> 1;
    const int a_col = (tid & 1) * 8;
    const int b_row = tid >> 4;
    const int b_col = (tid & 15) * 8;

    float acc[8][8];
    #pragma unroll
    for (int i = 0; i < 8; i++)
        #pragma unroll
        for (int j = 0; j < 8; j++)
            acc[i][j] = 0.0f;

    const int g_arow = block_row + a_row;
    const bool a_valid = (g_arow < N_NODES);

    for (int kt = 0; kt < IN_F; kt += BK) {
        {
            float4 v0, v1;
            if (a_valid) {
                const float* xp = x + (size_t)g_arow * IN_F + kt + a_col;
                v0 = *(const float4*)(xp);
                v1 = *(const float4*)(xp + 4);
            } else {
                v0 = make_float4(0.f, 0.f, 0.f, 0.f);
                v1 = v0;
            }
            As[(a_col + 0) * 128 + a_row] = v0.x;
            As[(a_col + 1) * 128 + a_row] = v0.y;
            As[(a_col + 2) * 128 + a_row] = v0.z;
            As[(a_col + 3) * 128 + a_row] = v0.w;
            As[(a_col + 4) * 128 + a_row] = v1.x;
            As[(a_col + 5) * 128 + a_row] = v1.y;
            As[(a_col + 6) * 128 + a_row] = v1.z;
            As[(a_col + 7) * 128 + a_row] = v1.w;
        }
        {
            const float* wp = w + (size_t)(kt + b_row) * OUT_F + b_col;
            float4 v0 = *(const float4*)(wp);
            float4 v1 = *(const float4*)(wp + 4);
            *(float4*)(&Bs[b_row * 128 + b_col])     = v0;
            *(float4*)(&Bs[b_row * 128 + b_col + 4]) = v1;
        }
        __syncthreads();

        #pragma unroll
        for (int k = 0; k < BK; k++) {
            float a[8], b[8];
            float4 av0 = *(const float4*)(&As[k * 128 + ty * 8]);
            float4 av1 = *(const float4*)(&As[k * 128 + ty * 8 + 4]);
            float4 bv0 = *(const float4*)(&Bs[k * 128 + tx * 8]);
            float4 bv1 = *(const float4*)(&Bs[k * 128 + tx * 8 + 4]);
            a[0]=av0.x; a[1]=av0.y; a[2]=av0.z; a[3]=av0.w;
            a[4]=av1.x; a[5]=av1.y; a[6]=av1.z; a[7]=av1.w;
            b[0]=bv0.x; b[1]=bv0.y; b[2]=bv0.z; b[3]=bv0.w;
            b[4]=bv1.x; b[5]=bv1.y; b[6]=bv1.z; b[7]=bv1.w;
            #pragma unroll
            for (int i = 0; i < 8; i++)
                #pragma unroll
                for (int j = 0; j < 8; j++)
                    acc[i][j] = fmaf(a[i], b[j], acc[i][j]);
        }
        __syncthreads();
    }

    #pragma unroll
    for (int i = 0; i < 8; i++) {
        const int gr = block_row + ty * 8 + i;
        if (gr < N_NODES) {
            uint2* sp = (uint2*)(g_support_h + (size_t)gr * OUT_F + tx * 8);
            __half2 h0 = __floats2half2_rn(acc[i][0], acc[i][1]);
            __half2 h1 = __floats2half2_rn(acc[i][2], acc[i][3]);
            __half2 h2 = __floats2half2_rn(acc[i][4], acc[i][5]);
            __half2 h3 = __floats2half2_rn(acc[i][6], acc[i][7]);
            sp[0] = make_uint2(h2_bits(h0), h2_bits(h1));
            sp[1] = make_uint2(h2_bits(h2), h2_bits(h3));
        }
    }
#endif
}

// ---------------------------------------------------------------------------
// CSR build: 3 launches (histogram, scan, permute).
// Counts are zeroed BY THE SCAN after reading (self-restoring state);
// scan flags are reset by the aggregate kernel. First call sees the
// zero-initialized module state; every replay sees the same state.
// ---------------------------------------------------------------------------
__global__ void gcn_histogram_kernel(const int* __restrict__ edge_rows)
{
    int e = blockIdx.x * blockDim.x + threadIdx.x;
    if (e < N_EDGES) atomicAdd(&g_counts[edge_rows[e]], 1);
}

// Single-pass decoupled-lookback exclusive scan; also re-zeros g_counts.
// grid = NUM_CHUNKS (49) blocks, all co-resident -> spin-safe.
__global__ __launch_bounds__(1024) void gcn_scan_kernel()
{
    __shared__ int warp_sums[32];
    __shared__ int s_total;
    __shared__ int s_base;

    const int bid  = blockIdx.x;
    const int i    = bid * SCAN_CHUNK + threadIdx.x;
    const int lane = threadIdx.x & 31;
    const int warp = threadIdx.x >> 5;

    int v = 0;
    if (i < N_NODES) {
        v = g_counts[i];
        g_counts[i] = 0;     // restore for next replay's histogram
    }

    int incl = v;
    #pragma unroll
    for (int off = 1; off < 32; off <<= 1) {
        int t = __shfl_up_sync(0xffffffffu, incl, off);
        if (lane >= off) incl += t;
    }
    if (lane == 31) warp_sums[warp] = incl;
    __syncthreads();
    if (warp == 0) {
        int w = warp_sums[lane];
        int wi = w;
        #pragma unroll
        for (int off = 1; off < 32; off <<= 1) {
            int t = __shfl_up_sync(0xffffffffu, wi, off);
            if (lane >= off) wi += t;
        }
        if (lane == 31) s_total = wi;
        warp_sums[lane] = wi - w;
    }
    __syncthreads();

    if (threadIdx.x == 0) {
        g_scan_partial[bid] = s_total;
        __threadfence();
        atomicExch(&g_scan_flag[bid], 1);
    }

    if (warp == 0) {
        int base = 0;
        for (int b = lane; b < bid; b += 32) {
            while (atomicAdd(&g_scan_flag[b], 0) == 0) {}
            base += g_scan_partial[b];
        }
        #pragma unroll
        for (int off = 16; off > 0; off >>= 1)
            base += __shfl_down_sync(0xffffffffu, base, off);
        if (lane == 0) s_base = base;
    }
    __syncthreads();

    if (i < N_NODES) {
        int o = s_base + warp_sums[warp] + (incl - v);
        g_offsets[i] = o;
        g_cursor[i]  = o;
    }
    if (bid == NUM_CHUNKS - 1 && threadIdx.x == 0)
        g_offsets[N_NODES] = s_base + s_total;
}

__global__ void gcn_permute_kernel(const int*   __restrict__ edge_rows,
                                   const int*   __restrict__ edge_cols,
                                   const float* __restrict__ edge_vals)
{
    int e = blockIdx.x * blockDim.x + threadIdx.x;
    if (e < N_EDGES) {
        int r = edge_rows[e];
        int pos = atomicAdd(&g_cursor[r], 1);
        g_sorted[pos] = make_int2(edge_cols[e], __float_as_int(edge_vals[e]));
    }
}

// ---------------------------------------------------------------------------
// Aggregate: one warp per node; fp16 gathers, fp32 accumulation.
// Resets scan flags for the next replay (runs strictly after scan).
// ---------------------------------------------------------------------------
__device__ __forceinline__ void agg_fma(float4& acc, float v, uint2 m)
{
    __half2 ha, hb;
    memcpy(&ha, &m.x, 4);
    memcpy(&hb, &m.y, 4);
    const float2 fa = __half22float2(ha);
    const float2 fb = __half22float2(hb);
    acc.x = fmaf(v, fa.x, acc.x);
    acc.y = fmaf(v, fa.y, acc.y);
    acc.z = fmaf(v, fb.x, acc.z);
    acc.w = fmaf(v, fb.y, acc.w);
}

__global__ __launch_bounds__(256) void gcn_aggregate_kernel(
    float* __restrict__ out,
    const float* __restrict__ bias)
{
    if (blockIdx.x == 0 && threadIdx.x < NUM_CHUNKS)
        g_scan_flag[threadIdx.x] = 0;

    const int warp_id = (blockIdx.x * blockDim.x + threadIdx.x) >> 5;
    const int lane    = threadIdx.x & 31;
    if (warp_id >= N_NODES) return;

    const int start = g_offsets[warp_id];
    const int end   = g_offsets[warp_id + 1];

    float4 acc = make_float4(0.f, 0.f, 0.f, 0.f);
    const uint2* sup = (const uint2*)g_support_h;

    for (int base = start; base < end; base += 32) {
        const int n = min(32, end - base);
        int2 ev = make_int2(0, 0);
        if (lane < n)
            ev = __ldg(&g_sorted[base + lane]);
        const int   c = ev.x;
        const float v = __int_as_float(ev.y);

        int j = 0;
        for (; j + 4 <= n; j += 4) {
            const int   c0 = __shfl_sync(0xffffffffu, c, j + 0);
            const int   c1 = __shfl_sync(0xffffffffu, c, j + 1);
            const int   c2 = __shfl_sync(0xffffffffu, c, j + 2);
            const int   c3 = __shfl_sync(0xffffffffu, c, j + 3);
            const float v0 = __shfl_sync(0xffffffffu, v, j + 0);
            const float v1 = __shfl_sync(0xffffffffu, v, j + 1);
            const float v2 = __shfl_sync(0xffffffffu, v, j + 2);
            const float v3 = __shfl_sync(0xffffffffu, v, j + 3);
            const uint2 m0 = __ldg(sup + (size_t)c0 * 32 + lane);
            const uint2 m1 = __ldg(sup + (size_t)c1 * 32 + lane);
            const uint2 m2 = __ldg(sup + (size_t)c2 * 32 + lane);
            const uint2 m3 = __ldg(sup + (size_t)c3 * 32 + lane);
            agg_fma(acc, v0, m0);
            agg_fma(acc, v1, m1);
            agg_fma(acc, v2, m2);
            agg_fma(acc, v3, m3);
        }
        for (; j < n; j++) {
            const int   cj = __shfl_sync(0xffffffffu, c, j);
            const float vj = __shfl_sync(0xffffffffu, v, j);
            const uint2 m = __ldg(sup + (size_t)cj * 32 + lane);
            agg_fma(acc, vj, m);
        }
    }

    const float4 b = __ldg(((const float4*)bias) + lane);
    acc.x += b.x; acc.y += b.y; acc.z += b.z; acc.w += b.w;
    ((float4*)out)[(size_t)warp_id * 32 + lane] = acc;
}

// ---------------------------------------------------------------------------
// kernel_launch: GEMM on main stream; CSR build (3 launches) on side stream;
// join before aggregate.
// Inputs (metadata order): x, edge_rows, edge_cols, edge_vals, weight, bias
// ---------------------------------------------------------------------------
extern "C" void kernel_launch(void* const* d_in, const int* in_sizes, int n_in,
                              void* d_out, int out_size)
{
    const float* x         = (const float*)d_in[0];
    const int*   edge_rows = (const int*)  d_in[1];
    const int*   edge_cols = (const int*)  d_in[2];
    const float* edge_vals = (const float*)d_in[3];
    const float* weight    = (const float*)d_in[4];
    const float* bias      = (const float*)d_in[5];
    float*       out       = (float*)d_out;

    static cudaStream_t s_side = nullptr;
    static cudaEvent_t  ev_fork = nullptr;
    static cudaEvent_t  ev_join = nullptr;
    if (s_side == nullptr) {
        cudaStreamCreateWithFlags(&s_side, cudaStreamNonBlocking);
        cudaEventCreateWithFlags(&ev_fork, cudaEventDisableTiming);
        cudaEventCreateWithFlags(&ev_join, cudaEventDisableTiming);
        cudaFuncSetAttribute(gcn_gemm_tc_kernel,
                             cudaFuncAttributeMaxDynamicSharedMemorySize, SM_TOTAL);
    }

    // Fork
    cudaEventRecord(ev_fork, 0);
    cudaStreamWaitEvent(s_side, ev_fork, 0);

    // Branch A (main): GEMM
    gcn_gemm_tc_kernel<<<(N_NODES + 127) / 128, 256, SM_TOTAL>>>(x, weight);

    // Branch B (side): CSR build (histogram -> scan -> permute)
    gcn_histogram_kernel<<<(N_EDGES + 255) / 256, 256, 0, s_side>>>(edge_rows);
    gcn_scan_kernel<<<NUM_CHUNKS, 1024, 0, s_side>>>();
    gcn_permute_kernel<<<(N_EDGES + 255) / 256, 256, 0, s_side>>>(
        edge_rows, edge_cols, edge_vals);
    cudaEventRecord(ev_join, s_side);

    // Join + aggregate
    cudaStreamWaitEvent(0, ev_join, 0);
    {
        const int warps_per_block = 256 / 32;
        const int blocks = (N_NODES + warps_per_block - 1) / warps_per_block;
        gcn_aggregate_kernel<<<blocks, 256>>>(out, bias);
    }
}